// round 14
// baseline (speedup 1.0000x reference)
#include <cuda_runtime.h>
#include <math.h>

#define MAXN 50000
#define MAXE 800000
#define NSEG 64

// ---------------- scratch (device globals; no allocations allowed) ----------
__device__ int      g_cnt[MAXN];
__device__ int      g_rowptr[MAXN + 1];
__device__ int      g_cursor[MAXN];
__device__ int      g_col[MAXE];
__device__ int      g_bsums[64];
__device__ int      g_boff[65];
__device__ float    g_h[MAXN * 128];     // GAT features (x @ W_gat)
__device__ float    g_out1[MAXN * 128];  // post-GAT node features
__device__ float    g_h2[MAXN * 128];    // out1 @ W_gcn
__device__ float    g_out2[MAXN * 128];  // post-GCN node features
__device__ float    g_asrc[MAXN * 4];
__device__ float    g_adst[MAXN * 4];
__device__ float    g_dinv[MAXN];
__device__ float    g_gate[MAXN];
__device__ float    g_wnode[MAXN];
__device__ unsigned g_gmax[NSEG];
__device__ float    g_gsum[NSEG];
__device__ float    g_grep[NSEG * 128];

// ---------------- helpers ----------------------------------------------------
__device__ __forceinline__ float lrelu(float x) { return x > 0.f ? x : 0.2f * x; }
__device__ __forceinline__ float elu(float x)   { return x > 0.f ? x : expm1f(x); }
__device__ __forceinline__ float sel4(float4 v, int h) {
    return h == 0 ? v.x : h == 1 ? v.y : h == 2 ? v.z : v.w;
}
__device__ __forceinline__ unsigned fenc(float f) {
    unsigned u = __float_as_uint(f);
    return (u & 0x80000000u) ? ~u : (u | 0x80000000u);
}
__device__ __forceinline__ float fdec(unsigned u) {
    return (u & 0x80000000u) ? __uint_as_float(u ^ 0x80000000u) : __uint_as_float(~u);
}

// ---------------- init --------------------------------------------------------
__global__ void k_init(int n) {
    int i = blockIdx.x * blockDim.x + threadIdx.x;
    if (i < n) g_cnt[i] = 0;
    if (i < NSEG) { g_gmax[i] = 0x007FFFFFu; g_gsum[i] = 0.f; }  // enc(-inf)
    if (i < NSEG * 128) g_grep[i] = 0.f;
}

// ---------------- CSR build ----------------------------------------------------
__global__ void k_count(const int* __restrict__ dst, int e) {
    int i = blockIdx.x * blockDim.x + threadIdx.x;
    if (i < e) atomicAdd(&g_cnt[dst[i]], 1);
}

__global__ void k_scan1(int n) {  // 1024 threads/block: exclusive scan within block
    int tid = threadIdx.x;
    int gid = blockIdx.x * 1024 + tid;
    int v = (gid < n) ? g_cnt[gid] : 0;
    int x = v;
    int lane = tid & 31, wid = tid >> 5;
    #pragma unroll
    for (int off = 1; off < 32; off <<= 1) {
        int y = __shfl_up_sync(0xFFFFFFFFu, x, off);
        if (lane >= off) x += y;
    }
    __shared__ int ws[32];
    if (lane == 31) ws[wid] = x;
    __syncthreads();
    if (wid == 0) {
        int s = ws[lane];
        #pragma unroll
        for (int off = 1; off < 32; off <<= 1) {
            int y = __shfl_up_sync(0xFFFFFFFFu, s, off);
            if (lane >= off) s += y;
        }
        ws[lane] = s;
    }
    __syncthreads();
    int add = wid ? ws[wid - 1] : 0;
    int incl = x + add;
    if (gid < n) g_rowptr[gid] = incl - v;
    if (tid == 1023) g_bsums[blockIdx.x] = incl;
}

__global__ void k_scan2(int nb) {
    if (threadIdx.x == 0 && blockIdx.x == 0) {
        int run = 0;
        for (int b = 0; b < nb; b++) { g_boff[b] = run; run += g_bsums[b]; }
        g_boff[nb] = run;
    }
}

__global__ void k_scan3(int n) {
    int gid = blockIdx.x * 1024 + threadIdx.x;
    if (gid < n) {
        int v = g_rowptr[gid] + g_boff[blockIdx.x];
        g_rowptr[gid] = v;
        g_cursor[gid] = v;
    }
    if (gid == 0) g_rowptr[n] = g_boff[gridDim.x];
}

__global__ void k_fill(const int* __restrict__ src, const int* __restrict__ dst, int e) {
    int i = blockIdx.x * blockDim.x + threadIdx.x;
    if (i < e) {
        int d = dst[i];
        int p = atomicAdd(&g_cursor[d], 1);
        g_col[p] = src[i];
    }
}

// ---------------- GEMM: C[n,128] = A[n,128] @ B[128,128] (fp32, 8x8 microtile) --
__global__ __launch_bounds__(256) void k_gemm128(
    const float* __restrict__ A, const float* __restrict__ B,
    float* __restrict__ C, int n) {
    __shared__ float As[8][128];
    __shared__ float Bs[8][128];
    int tid = threadIdx.x;
    int tr = tid >> 4;        // 0..15
    int tc = tid & 15;        // 0..15
    int rowBase = blockIdx.x * 128;

    float acc[8][8];
    #pragma unroll
    for (int i = 0; i < 8; i++)
        #pragma unroll
        for (int j = 0; j < 8; j++) acc[i][j] = 0.f;

    int la_r = tid >> 1;           // 0..127
    int la_k = (tid & 1) * 4;      // 0 or 4
    int lb_k = tid >> 5;           // 0..7
    int lb_n = (tid & 31) * 4;     // 0..124

    for (int k0 = 0; k0 < 128; k0 += 8) {
        int gr = rowBase + la_r;
        float4 av = make_float4(0.f, 0.f, 0.f, 0.f);
        if (gr < n) av = *(const float4*)&A[(long)gr * 128 + k0 + la_k];
        As[la_k + 0][la_r] = av.x;
        As[la_k + 1][la_r] = av.y;
        As[la_k + 2][la_r] = av.z;
        As[la_k + 3][la_r] = av.w;
        float4 bv = *(const float4*)&B[(k0 + lb_k) * 128 + lb_n];
        *(float4*)&Bs[lb_k][lb_n] = bv;
        __syncthreads();
        #pragma unroll
        for (int kk = 0; kk < 8; kk++) {
            float4 a0 = *(const float4*)&As[kk][tr * 8];
            float4 a1 = *(const float4*)&As[kk][tr * 8 + 4];
            float4 b0 = *(const float4*)&Bs[kk][tc * 8];
            float4 b1 = *(const float4*)&Bs[kk][tc * 8 + 4];
            float a[8] = {a0.x, a0.y, a0.z, a0.w, a1.x, a1.y, a1.z, a1.w};
            float b[8] = {b0.x, b0.y, b0.z, b0.w, b1.x, b1.y, b1.z, b1.w};
            #pragma unroll
            for (int i = 0; i < 8; i++)
                #pragma unroll
                for (int j = 0; j < 8; j++) acc[i][j] += a[i] * b[j];
        }
        __syncthreads();
    }
    #pragma unroll
    for (int i = 0; i < 8; i++) {
        int gr = rowBase + tr * 8 + i;
        if (gr < n) {
            float4 o0 = make_float4(acc[i][0], acc[i][1], acc[i][2], acc[i][3]);
            float4 o1 = make_float4(acc[i][4], acc[i][5], acc[i][6], acc[i][7]);
            *(float4*)&C[(long)gr * 128 + tc * 8] = o0;
            *(float4*)&C[(long)gr * 128 + tc * 8 + 4] = o1;
        }
    }
}

// ---------------- attention logits per node ------------------------------------
__global__ void k_attn(const float* __restrict__ attsrc, const float* __restrict__ attdst, int n) {
    int w = (blockIdx.x * blockDim.x + threadIdx.x) >> 5;
    int lane = threadIdx.x & 31;
    if (w >= n) return;
    float4 hv = *(const float4*)&g_h[(long)w * 128 + lane * 4];
    float4 s4 = *(const float4*)&attsrc[lane * 4];
    float4 d4 = *(const float4*)&attdst[lane * 4];
    float ps = hv.x * s4.x + hv.y * s4.y + hv.z * s4.z + hv.w * s4.w;
    float pd = hv.x * d4.x + hv.y * d4.y + hv.z * d4.z + hv.w * d4.w;
    #pragma unroll
    for (int off = 4; off; off >>= 1) {
        ps += __shfl_xor_sync(0xFFFFFFFFu, ps, off);
        pd += __shfl_xor_sync(0xFFFFFFFFu, pd, off);
    }
    if ((lane & 7) == 0) {
        g_asrc[w * 4 + (lane >> 3)] = ps;
        g_adst[w * 4 + (lane >> 3)] = pd;
    }
}

// ---------------- GAT aggregation: warp per dst node ----------------------------
__global__ __launch_bounds__(256) void k_gat(
    const float* __restrict__ b_gat, const float* __restrict__ bn1w,
    const float* __restrict__ bn1b, int n) {
    int i = (blockIdx.x * blockDim.x + threadIdx.x) >> 5;
    int lane = threadIdx.x & 31;
    if (i >= n) return;
    int beg = g_rowptr[i], end = g_rowptr[i + 1];

    float4 ad  = *(const float4*)&g_adst[i * 4];
    float4 asi = *(const float4*)&g_asrc[i * 4];
    float4 sl;
    sl.x = lrelu(asi.x + ad.x); sl.y = lrelu(asi.y + ad.y);
    sl.z = lrelu(asi.z + ad.z); sl.w = lrelu(asi.w + ad.w);

    // pass 1: max over self-loop + incoming edges
    float4 mx = sl;
    for (int e = beg + lane; e < end; e += 32) {
        int s = g_col[e];
        float4 v = *(const float4*)&g_asrc[s * 4];
        v.x = lrelu(v.x + ad.x); v.y = lrelu(v.y + ad.y);
        v.z = lrelu(v.z + ad.z); v.w = lrelu(v.w + ad.w);
        mx.x = fmaxf(mx.x, v.x); mx.y = fmaxf(mx.y, v.y);
        mx.z = fmaxf(mx.z, v.z); mx.w = fmaxf(mx.w, v.w);
    }
    #pragma unroll
    for (int off = 16; off; off >>= 1) {
        mx.x = fmaxf(mx.x, __shfl_xor_sync(0xFFFFFFFFu, mx.x, off));
        mx.y = fmaxf(mx.y, __shfl_xor_sync(0xFFFFFFFFu, mx.y, off));
        mx.z = fmaxf(mx.z, __shfl_xor_sync(0xFFFFFFFFu, mx.z, off));
        mx.w = fmaxf(mx.w, __shfl_xor_sync(0xFFFFFFFFu, mx.w, off));
    }

    // pass 2: sum of exp (self-loop counted once on lane 0)
    float4 sm = make_float4(0.f, 0.f, 0.f, 0.f);
    if (lane == 0) {
        sm.x = __expf(sl.x - mx.x); sm.y = __expf(sl.y - mx.y);
        sm.z = __expf(sl.z - mx.z); sm.w = __expf(sl.w - mx.w);
    }
    for (int e = beg + lane; e < end; e += 32) {
        int s = g_col[e];
        float4 v = *(const float4*)&g_asrc[s * 4];
        sm.x += __expf(lrelu(v.x + ad.x) - mx.x);
        sm.y += __expf(lrelu(v.y + ad.y) - mx.y);
        sm.z += __expf(lrelu(v.z + ad.z) - mx.z);
        sm.w += __expf(lrelu(v.w + ad.w) - mx.w);
    }
    #pragma unroll
    for (int off = 16; off; off >>= 1) {
        sm.x += __shfl_xor_sync(0xFFFFFFFFu, sm.x, off);
        sm.y += __shfl_xor_sync(0xFFFFFFFFu, sm.y, off);
        sm.z += __shfl_xor_sync(0xFFFFFFFFu, sm.z, off);
        sm.w += __shfl_xor_sync(0xFFFFFFFFu, sm.w, off);
    }
    sm.x += 1e-16f; sm.y += 1e-16f; sm.z += 1e-16f; sm.w += 1e-16f;

    // pass 3: weighted feature accumulation. lane owns features [lane*4, lane*4+4)
    int head = lane >> 3;  // 32 feats per head, 4 feats per lane -> head = lane/8
    float m_h  = sel4(mx, head);
    float inv  = 1.f / sel4(sm, head);
    float ad_h = sel4(ad, head);

    const float4* hf = (const float4*)g_h;
    float a_self = __expf(sel4(sl, head) - m_h) * inv;
    float4 hv = hf[(long)i * 32 + lane];
    float4 acc = make_float4(a_self * hv.x, a_self * hv.y, a_self * hv.z, a_self * hv.w);

    for (int e = beg; e < end; e++) {
        int s = g_col[e];
        float a = lrelu(g_asrc[s * 4 + head] + ad_h);
        float alpha = __expf(a - m_h) * inv;
        float4 v = hf[(long)s * 32 + lane];
        acc.x += alpha * v.x; acc.y += alpha * v.y;
        acc.z += alpha * v.z; acc.w += alpha * v.w;
    }

    float4 bb = ((const float4*)b_gat)[lane];
    float4 w1 = ((const float4*)bn1w)[lane];
    float4 b1 = ((const float4*)bn1b)[lane];
    float4 o;
    o.x = elu(acc.x + bb.x) * w1.x + b1.x;
    o.y = elu(acc.y + bb.y) * w1.y + b1.y;
    o.z = elu(acc.z + bb.z) * w1.z + b1.z;
    o.w = elu(acc.w + bb.w) * w1.w + b1.w;
    ((float4*)g_out1)[(long)i * 32 + lane] = o;
    if (lane == 0) g_dinv[i] = rsqrtf((float)(end - beg + 1));
}

// ---------------- GCN aggregation + gate ---------------------------------------
__global__ __launch_bounds__(256) void k_gcn(
    const float* __restrict__ b_gcn, const float* __restrict__ bn2w,
    const float* __restrict__ bn2b, const float* __restrict__ Wgate,
    const float* __restrict__ bgate, int n) {
    int i = (blockIdx.x * blockDim.x + threadIdx.x) >> 5;
    int lane = threadIdx.x & 31;
    if (i >= n) return;
    int beg = g_rowptr[i], end = g_rowptr[i + 1];
    float di = g_dinv[i];
    const float4* h2 = (const float4*)g_h2;

    float4 v = h2[(long)i * 32 + lane];
    float s2 = di * di;  // self-loop norm
    float4 acc = make_float4(s2 * v.x, s2 * v.y, s2 * v.z, s2 * v.w);

    for (int e = beg; e < end; e++) {
        int s = g_col[e];
        float nm = di * g_dinv[s];
        float4 u = h2[(long)s * 32 + lane];
        acc.x += nm * u.x; acc.y += nm * u.y;
        acc.z += nm * u.z; acc.w += nm * u.w;
    }

    float4 bb = ((const float4*)b_gcn)[lane];
    float4 w2 = ((const float4*)bn2w)[lane];
    float4 b2 = ((const float4*)bn2b)[lane];
    float4 o;
    o.x = elu(acc.x + bb.x) * w2.x + b2.x;
    o.y = elu(acc.y + bb.y) * w2.y + b2.y;
    o.z = elu(acc.z + bb.z) * w2.z + b2.z;
    o.w = elu(acc.w + bb.w) * w2.w + b2.w;
    ((float4*)g_out2)[(long)i * 32 + lane] = o;

    float4 wg = ((const float4*)Wgate)[lane];
    float g = o.x * wg.x + o.y * wg.y + o.z * wg.z + o.w * wg.w;
    #pragma unroll
    for (int off = 16; off; off >>= 1) g += __shfl_xor_sync(0xFFFFFFFFu, g, off);
    if (lane == 0) g_gate[i] = g + bgate[0];
}

// ---------------- global-attention pooling -------------------------------------
__global__ void k_pool_max(const int* __restrict__ batch, int n) {
    int i = blockIdx.x * blockDim.x + threadIdx.x;
    if (i < n) atomicMax(&g_gmax[batch[i]], fenc(g_gate[i]));
}
__global__ void k_pool_sum(const int* __restrict__ batch, int n) {
    int i = blockIdx.x * blockDim.x + threadIdx.x;
    if (i < n) {
        int b = batch[i];
        float m = fdec(g_gmax[b]);
        if (!isfinite(m)) m = 0.f;
        float ex = __expf(g_gate[i] - m);
        g_wnode[i] = ex;
        atomicAdd(&g_gsum[b], ex);
    }
}
__global__ void k_pool_acc(const int* __restrict__ batch, int n) {
    int idx = blockIdx.x * blockDim.x + threadIdx.x;
    if (idx < n * 128) {
        int nn = idx >> 7;
        int c  = idx & 127;
        int b  = batch[nn];
        float w = g_wnode[nn] / (g_gsum[b] + 1e-16f);
        atomicAdd(&g_grep[b * 128 + c], w * g_out2[idx]);
    }
}
__global__ void k_final(const float* __restrict__ Wfc, const float* __restrict__ bfc,
                        float* __restrict__ out) {
    int g = blockIdx.x;
    int t = threadIdx.x;  // 128
    float v = g_grep[g * 128 + t] * Wfc[t];
    #pragma unroll
    for (int off = 16; off; off >>= 1) v += __shfl_xor_sync(0xFFFFFFFFu, v, off);
    __shared__ float s[4];
    if ((t & 31) == 0) s[t >> 5] = v;
    __syncthreads();
    if (t == 0) out[g] = s[0] + s[1] + s[2] + s[3] + bfc[0];
}

// ---------------- launcher ------------------------------------------------------
extern "C" void kernel_launch(void* const* d_in, const int* in_sizes, int n_in,
                              void* d_out, int out_size) {
    const float* x      = (const float*)d_in[0];
    const int*   ei     = (const int*)  d_in[1];
    const int*   batch  = (const int*)  d_in[2];
    const float* Wgat   = (const float*)d_in[3];
    const float* attsrc = (const float*)d_in[4];
    const float* attdst = (const float*)d_in[5];
    const float* bgat   = (const float*)d_in[6];
    const float* bn1w   = (const float*)d_in[7];
    const float* bn1b   = (const float*)d_in[8];
    const float* Wgcn   = (const float*)d_in[9];
    const float* bgcn   = (const float*)d_in[10];
    const float* bn2w   = (const float*)d_in[11];
    const float* bn2b   = (const float*)d_in[12];
    const float* Wgate  = (const float*)d_in[13];
    const float* bgate  = (const float*)d_in[14];
    const float* Wfc    = (const float*)d_in[15];
    const float* bfc    = (const float*)d_in[16];
    float* out = (float*)d_out;

    int n = in_sizes[0] / 128;
    int e = in_sizes[1] / 2;
    if (n > MAXN) n = MAXN;
    if (e > MAXE) e = MAXE;
    const int* src = ei;
    const int* dst = ei + e;

    float *ph, *pout1, *ph2;
    cudaGetSymbolAddress((void**)&ph,    g_h);
    cudaGetSymbolAddress((void**)&pout1, g_out1);
    cudaGetSymbolAddress((void**)&ph2,   g_h2);

    int nb = (n + 1023) / 1024;

    k_init <<<(n + 255) / 256, 256>>>(n);
    k_count<<<(e + 255) / 256, 256>>>(dst, e);
    k_scan1<<<nb, 1024>>>(n);
    k_scan2<<<1, 32>>>(nb);
    k_scan3<<<nb, 1024>>>(n);
    k_fill <<<(e + 255) / 256, 256>>>(src, dst, e);

    k_gemm128<<<(n + 127) / 128, 256>>>(x, Wgat, ph, n);
    k_attn   <<<(n * 32 + 255) / 256, 256>>>(attsrc, attdst, n);
    k_gat    <<<(n * 32 + 255) / 256, 256>>>(bgat, bn1w, bn1b, n);

    k_gemm128<<<(n + 127) / 128, 256>>>(pout1, Wgcn, ph2, n);
    k_gcn    <<<(n * 32 + 255) / 256, 256>>>(bgcn, bn2w, bn2b, Wgate, bgate, n);

    k_pool_max<<<(n + 255) / 256, 256>>>(batch, n);
    k_pool_sum<<<(n + 255) / 256, 256>>>(batch, n);
    k_pool_acc<<<(n * 128 + 255) / 256, 256>>>(batch, n);
    k_final   <<<NSEG, 128>>>(Wfc, bfc, out);
}

// round 15
// speedup vs baseline: 1.2808x; 1.2808x over previous
#include <cuda_runtime.h>
#include <math.h>

#define MAXN 50000
#define MAXE 800000
#define NSEG 64

// ---------------- scratch (device globals; no allocations allowed) ----------
__device__ int      g_cnt[MAXN];
__device__ int      g_rowptr[MAXN + 1];
__device__ int      g_cursor[MAXN];
__device__ int      g_col[MAXE];
__device__ int      g_bsums[64];
__device__ int      g_boff[65];
__device__ float    g_h[MAXN * 128];     // GAT features (x @ W_gat)
__device__ float    g_out1[MAXN * 128];  // post-GAT node features
__device__ float    g_h2[MAXN * 128];    // out1 @ W_gcn
__device__ float    g_out2[MAXN * 128];  // post-GCN node features
__device__ float    g_asrc[MAXN * 4];
__device__ float    g_adst[MAXN * 4];
__device__ float    g_dinv[MAXN];
__device__ float    g_gate[MAXN];
__device__ unsigned g_gmax[NSEG];
__device__ float    g_gsum[NSEG];
__device__ float    g_grep[NSEG * 128];

// ---------------- helpers ----------------------------------------------------
__device__ __forceinline__ float lrelu(float x) { return x > 0.f ? x : 0.2f * x; }
__device__ __forceinline__ float elu(float x)   { return x > 0.f ? x : expm1f(x); }
__device__ __forceinline__ float sel4(float4 v, int h) {
    return h == 0 ? v.x : h == 1 ? v.y : h == 2 ? v.z : v.w;
}
__device__ __forceinline__ unsigned fenc(float f) {
    unsigned u = __float_as_uint(f);
    return (u & 0x80000000u) ? ~u : (u | 0x80000000u);
}
__device__ __forceinline__ float fdec(unsigned u) {
    return (u & 0x80000000u) ? __uint_as_float(u ^ 0x80000000u) : __uint_as_float(~u);
}
// online softmax update / merge
__device__ __forceinline__ void onl(float& m, float& s, float v) {
    float nm = fmaxf(m, v);
    s = s * __expf(m - nm) + __expf(v - nm);
    m = nm;
}
__device__ __forceinline__ void comb(float& m, float& s, float mo, float so) {
    float nm = fmaxf(m, mo);
    s = s * __expf(m - nm) + so * __expf(mo - nm);
    m = nm;
}

// ---------------- init --------------------------------------------------------
__global__ void k_init(int n) {
    int i = blockIdx.x * blockDim.x + threadIdx.x;
    if (i < n) g_cnt[i] = 0;
    if (i < NSEG) { g_gmax[i] = 0x007FFFFFu; g_gsum[i] = 0.f; }  // enc(-inf)
    if (i < NSEG * 128) g_grep[i] = 0.f;
}

// ---------------- CSR build ----------------------------------------------------
__global__ void k_count(const int* __restrict__ dst, int e) {
    int i = blockIdx.x * blockDim.x + threadIdx.x;
    if (i < e) atomicAdd(&g_cnt[dst[i]], 1);
}

__global__ void k_scan1(int n) {  // 1024 threads/block: exclusive scan within block
    int tid = threadIdx.x;
    int gid = blockIdx.x * 1024 + tid;
    int v = (gid < n) ? g_cnt[gid] : 0;
    int x = v;
    int lane = tid & 31, wid = tid >> 5;
    #pragma unroll
    for (int off = 1; off < 32; off <<= 1) {
        int y = __shfl_up_sync(0xFFFFFFFFu, x, off);
        if (lane >= off) x += y;
    }
    __shared__ int ws[32];
    if (lane == 31) ws[wid] = x;
    __syncthreads();
    if (wid == 0) {
        int s = ws[lane];
        #pragma unroll
        for (int off = 1; off < 32; off <<= 1) {
            int y = __shfl_up_sync(0xFFFFFFFFu, s, off);
            if (lane >= off) s += y;
        }
        ws[lane] = s;
    }
    __syncthreads();
    int add = wid ? ws[wid - 1] : 0;
    int incl = x + add;
    if (gid < n) g_rowptr[gid] = incl - v;
    if (tid == 1023) g_bsums[blockIdx.x] = incl;
}

__global__ void k_scan2(int nb) {  // 64-thread parallel scan over block sums
    int tid = threadIdx.x;
    int lane = tid & 31, w = tid >> 5;
    int v = (tid < nb) ? g_bsums[tid] : 0;
    int x = v;
    #pragma unroll
    for (int off = 1; off < 32; off <<= 1) {
        int y = __shfl_up_sync(0xFFFFFFFFu, x, off);
        if (lane >= off) x += y;
    }
    __shared__ int t0;
    if (w == 0 && lane == 31) t0 = x;
    __syncthreads();
    if (w == 1) x += t0;
    g_boff[tid + 1] = x;
    if (tid == 0) g_boff[0] = 0;
}

__global__ void k_scan3(int n) {
    int gid = blockIdx.x * 1024 + threadIdx.x;
    if (gid < n) {
        int v = g_rowptr[gid] + g_boff[blockIdx.x];
        g_rowptr[gid] = v;
        g_cursor[gid] = v;
    }
    if (gid == 0) g_rowptr[n] = g_boff[gridDim.x];
}

__global__ void k_fill(const int* __restrict__ src, const int* __restrict__ dst, int e) {
    int i = blockIdx.x * blockDim.x + threadIdx.x;
    if (i < e) {
        int d = dst[i];
        int p = atomicAdd(&g_cursor[d], 1);
        g_col[p] = src[i];
    }
}

// ---------------- GEMM: C[n,128] = A[n,128] @ B[128,128] (fp32, 8x8 microtile) --
// Optional epilogue (DO_ATT): per-row dot with att_src/att_dst -> g_asrc/g_adst.
template <bool DO_ATT>
__global__ __launch_bounds__(256) void k_gemm128(
    const float* __restrict__ A, const float* __restrict__ B,
    float* __restrict__ C, const float* __restrict__ attsrc,
    const float* __restrict__ attdst, int n) {
    __shared__ float As[8][128];
    __shared__ float Bs[8][128];
    int tid = threadIdx.x;
    int tr = tid >> 4;        // 0..15
    int tc = tid & 15;        // 0..15
    int rowBase = blockIdx.x * 128;

    float acc[8][8];
    #pragma unroll
    for (int i = 0; i < 8; i++)
        #pragma unroll
        for (int j = 0; j < 8; j++) acc[i][j] = 0.f;

    int la_r = tid >> 1;           // 0..127
    int la_k = (tid & 1) * 4;      // 0 or 4
    int lb_k = tid >> 5;           // 0..7
    int lb_n = (tid & 31) * 4;     // 0..124

    for (int k0 = 0; k0 < 128; k0 += 8) {
        int gr = rowBase + la_r;
        float4 av = make_float4(0.f, 0.f, 0.f, 0.f);
        if (gr < n) av = *(const float4*)&A[(long)gr * 128 + k0 + la_k];
        As[la_k + 0][la_r] = av.x;
        As[la_k + 1][la_r] = av.y;
        As[la_k + 2][la_r] = av.z;
        As[la_k + 3][la_r] = av.w;
        float4 bv = *(const float4*)&B[(k0 + lb_k) * 128 + lb_n];
        *(float4*)&Bs[lb_k][lb_n] = bv;
        __syncthreads();
        #pragma unroll
        for (int kk = 0; kk < 8; kk++) {
            float4 a0 = *(const float4*)&As[kk][tr * 8];
            float4 a1 = *(const float4*)&As[kk][tr * 8 + 4];
            float4 b0 = *(const float4*)&Bs[kk][tc * 8];
            float4 b1 = *(const float4*)&Bs[kk][tc * 8 + 4];
            float a[8] = {a0.x, a0.y, a0.z, a0.w, a1.x, a1.y, a1.z, a1.w};
            float b[8] = {b0.x, b0.y, b0.z, b0.w, b1.x, b1.y, b1.z, b1.w};
            #pragma unroll
            for (int i = 0; i < 8; i++)
                #pragma unroll
                for (int j = 0; j < 8; j++) acc[i][j] += a[i] * b[j];
        }
        __syncthreads();
    }
    #pragma unroll
    for (int i = 0; i < 8; i++) {
        int gr = rowBase + tr * 8 + i;
        if (gr < n) {
            float4 o0 = make_float4(acc[i][0], acc[i][1], acc[i][2], acc[i][3]);
            float4 o1 = make_float4(acc[i][4], acc[i][5], acc[i][6], acc[i][7]);
            *(float4*)&C[(long)gr * 128 + tc * 8] = o0;
            *(float4*)&C[(long)gr * 128 + tc * 8 + 4] = o1;
        }
    }
    if (DO_ATT) {
        int head = tc >> 2;  // cols tc*8..tc*8+7 all lie in one head of 32
        float4 s0 = ((const float4*)attsrc)[tc * 2];
        float4 s1 = ((const float4*)attsrc)[tc * 2 + 1];
        float4 d0 = ((const float4*)attdst)[tc * 2];
        float4 d1 = ((const float4*)attdst)[tc * 2 + 1];
        #pragma unroll
        for (int i = 0; i < 8; i++) {
            float ps = acc[i][0] * s0.x + acc[i][1] * s0.y + acc[i][2] * s0.z + acc[i][3] * s0.w
                     + acc[i][4] * s1.x + acc[i][5] * s1.y + acc[i][6] * s1.z + acc[i][7] * s1.w;
            float pd = acc[i][0] * d0.x + acc[i][1] * d0.y + acc[i][2] * d0.z + acc[i][3] * d0.w
                     + acc[i][4] * d1.x + acc[i][5] * d1.y + acc[i][6] * d1.z + acc[i][7] * d1.w;
            ps += __shfl_xor_sync(0xFFFFFFFFu, ps, 1);
            ps += __shfl_xor_sync(0xFFFFFFFFu, ps, 2);
            pd += __shfl_xor_sync(0xFFFFFFFFu, pd, 1);
            pd += __shfl_xor_sync(0xFFFFFFFFu, pd, 2);
            int gr = rowBase + tr * 8 + i;
            if ((tc & 3) == 0 && gr < n) {
                g_asrc[gr * 4 + head] = ps;
                g_adst[gr * 4 + head] = pd;
            }
        }
    }
}

// ---------------- GAT aggregation: warp per dst node, online softmax ------------
__global__ __launch_bounds__(256) void k_gat(
    const float* __restrict__ b_gat, const float* __restrict__ bn1w,
    const float* __restrict__ bn1b, int n) {
    int i = (blockIdx.x * blockDim.x + threadIdx.x) >> 5;
    int lane = threadIdx.x & 31;
    if (i >= n) return;
    int beg = g_rowptr[i], end = g_rowptr[i + 1];

    float4 ad  = *(const float4*)&g_adst[i * 4];
    float4 asi = *(const float4*)&g_asrc[i * 4];
    float4 sl;
    sl.x = lrelu(asi.x + ad.x); sl.y = lrelu(asi.y + ad.y);
    sl.z = lrelu(asi.z + ad.z); sl.w = lrelu(asi.w + ad.w);

    // single online-softmax pass over edges (self-loop seeded on lane 0)
    float4 mx, sm;
    if (lane == 0) { mx = sl; sm = make_float4(1.f, 1.f, 1.f, 1.f); }
    else { mx = make_float4(-1e30f, -1e30f, -1e30f, -1e30f);
           sm = make_float4(0.f, 0.f, 0.f, 0.f); }
    for (int e = beg + lane; e < end; e += 32) {
        int s = g_col[e];
        float4 v = *(const float4*)&g_asrc[s * 4];
        onl(mx.x, sm.x, lrelu(v.x + ad.x));
        onl(mx.y, sm.y, lrelu(v.y + ad.y));
        onl(mx.z, sm.z, lrelu(v.z + ad.z));
        onl(mx.w, sm.w, lrelu(v.w + ad.w));
    }
    #pragma unroll
    for (int off = 16; off; off >>= 1) {
        float mox = __shfl_xor_sync(0xFFFFFFFFu, mx.x, off);
        float sox = __shfl_xor_sync(0xFFFFFFFFu, sm.x, off);
        float moy = __shfl_xor_sync(0xFFFFFFFFu, mx.y, off);
        float soy = __shfl_xor_sync(0xFFFFFFFFu, sm.y, off);
        float moz = __shfl_xor_sync(0xFFFFFFFFu, mx.z, off);
        float soz = __shfl_xor_sync(0xFFFFFFFFu, sm.z, off);
        float mow = __shfl_xor_sync(0xFFFFFFFFu, mx.w, off);
        float sow = __shfl_xor_sync(0xFFFFFFFFu, sm.w, off);
        comb(mx.x, sm.x, mox, sox);
        comb(mx.y, sm.y, moy, soy);
        comb(mx.z, sm.z, moz, soz);
        comb(mx.w, sm.w, mow, sow);
    }
    sm.x += 1e-16f; sm.y += 1e-16f; sm.z += 1e-16f; sm.w += 1e-16f;

    // feature pass: lane owns features [lane*4, lane*4+4); head = lane/8
    int head = lane >> 3;
    float m_h  = sel4(mx, head);
    float inv  = 1.f / sel4(sm, head);
    float ad_h = sel4(ad, head);

    const float4* hf = (const float4*)g_h;
    float a_self = __expf(sel4(sl, head) - m_h) * inv;
    float4 hv = hf[(long)i * 32 + lane];
    float4 acc = make_float4(a_self * hv.x, a_self * hv.y, a_self * hv.z, a_self * hv.w);

    int sA = (beg < end) ? g_col[beg] : 0;
    for (int e = beg; e < end; e++) {
        int s = sA;
        if (e + 1 < end) sA = g_col[e + 1];
        float a = lrelu(g_asrc[s * 4 + head] + ad_h);
        float alpha = __expf(a - m_h) * inv;
        float4 v = hf[(long)s * 32 + lane];
        acc.x += alpha * v.x; acc.y += alpha * v.y;
        acc.z += alpha * v.z; acc.w += alpha * v.w;
    }

    float4 bb = ((const float4*)b_gat)[lane];
    float4 w1 = ((const float4*)bn1w)[lane];
    float4 b1 = ((const float4*)bn1b)[lane];
    float4 o;
    o.x = elu(acc.x + bb.x) * w1.x + b1.x;
    o.y = elu(acc.y + bb.y) * w1.y + b1.y;
    o.z = elu(acc.z + bb.z) * w1.z + b1.z;
    o.w = elu(acc.w + bb.w) * w1.w + b1.w;
    ((float4*)g_out1)[(long)i * 32 + lane] = o;
    if (lane == 0) g_dinv[i] = rsqrtf((float)(end - beg + 1));
}

// ---------------- GCN aggregation + gate + pool max -----------------------------
__global__ __launch_bounds__(256) void k_gcn(
    const float* __restrict__ b_gcn, const float* __restrict__ bn2w,
    const float* __restrict__ bn2b, const float* __restrict__ Wgate,
    const float* __restrict__ bgate, const int* __restrict__ batch, int n) {
    int i = (blockIdx.x * blockDim.x + threadIdx.x) >> 5;
    int lane = threadIdx.x & 31;
    if (i >= n) return;
    int beg = g_rowptr[i], end = g_rowptr[i + 1];
    float di = g_dinv[i];
    const float4* h2 = (const float4*)g_h2;

    float4 v = h2[(long)i * 32 + lane];
    float s2 = di * di;  // self-loop norm
    float4 acc = make_float4(s2 * v.x, s2 * v.y, s2 * v.z, s2 * v.w);

    int sA = (beg < end) ? g_col[beg] : 0;
    for (int e = beg; e < end; e++) {
        int s = sA;
        if (e + 1 < end) sA = g_col[e + 1];
        float nm = di * g_dinv[s];
        float4 u = h2[(long)s * 32 + lane];
        acc.x += nm * u.x; acc.y += nm * u.y;
        acc.z += nm * u.z; acc.w += nm * u.w;
    }

    float4 bb = ((const float4*)b_gcn)[lane];
    float4 w2 = ((const float4*)bn2w)[lane];
    float4 b2 = ((const float4*)bn2b)[lane];
    float4 o;
    o.x = elu(acc.x + bb.x) * w2.x + b2.x;
    o.y = elu(acc.y + bb.y) * w2.y + b2.y;
    o.z = elu(acc.z + bb.z) * w2.z + b2.z;
    o.w = elu(acc.w + bb.w) * w2.w + b2.w;
    ((float4*)g_out2)[(long)i * 32 + lane] = o;

    float4 wg = ((const float4*)Wgate)[lane];
    float g = o.x * wg.x + o.y * wg.y + o.z * wg.z + o.w * wg.w;
    #pragma unroll
    for (int off = 16; off; off >>= 1) g += __shfl_xor_sync(0xFFFFFFFFu, g, off);
    if (lane == 0) {
        float gg = g + bgate[0];
        g_gate[i] = gg;
        atomicMax(&g_gmax[batch[i]], fenc(gg));
    }
}

// ---------------- pooling: block-local accumulation (batch is sorted) -----------
// 128 threads/block (one per channel), 64 nodes per block; flush atomics only on
// segment change -> ~200K atomics instead of 6.4M.
__global__ __launch_bounds__(128) void k_pool(const int* __restrict__ batch, int n) {
    int c = threadIdx.x;
    int nbeg = blockIdx.x * 64;
    int nend = nbeg + 64; if (nend > n) nend = n;
    if (nbeg >= n) return;
    int curb = batch[nbeg];
    float m = fdec(g_gmax[curb]); if (!isfinite(m)) m = 0.f;
    float acc = 0.f, exsum = 0.f;
    for (int nn = nbeg; nn < nend; nn++) {
        int b = batch[nn];
        if (b != curb) {
            atomicAdd(&g_grep[curb * 128 + c], acc);
            if (c == 0) atomicAdd(&g_gsum[curb], exsum);
            acc = 0.f; exsum = 0.f; curb = b;
            m = fdec(g_gmax[curb]); if (!isfinite(m)) m = 0.f;
        }
        float ex = __expf(g_gate[nn] - m);
        exsum += ex;
        acc += ex * g_out2[(long)nn * 128 + c];
    }
    atomicAdd(&g_grep[curb * 128 + c], acc);
    if (c == 0) atomicAdd(&g_gsum[curb], exsum);
}

__global__ void k_final(const float* __restrict__ Wfc, const float* __restrict__ bfc,
                        float* __restrict__ out) {
    int g = blockIdx.x;
    int t = threadIdx.x;  // 128
    float v = g_grep[g * 128 + t] * Wfc[t];
    #pragma unroll
    for (int off = 16; off; off >>= 1) v += __shfl_xor_sync(0xFFFFFFFFu, v, off);
    __shared__ float s[4];
    if ((t & 31) == 0) s[t >> 5] = v;
    __syncthreads();
    if (t == 0) out[g] = (s[0] + s[1] + s[2] + s[3]) / (g_gsum[g] + 1e-16f) + bfc[0];
}

// ---------------- launcher ------------------------------------------------------
extern "C" void kernel_launch(void* const* d_in, const int* in_sizes, int n_in,
                              void* d_out, int out_size) {
    const float* x      = (const float*)d_in[0];
    const int*   ei     = (const int*)  d_in[1];
    const int*   batch  = (const int*)  d_in[2];
    const float* Wgat   = (const float*)d_in[3];
    const float* attsrc = (const float*)d_in[4];
    const float* attdst = (const float*)d_in[5];
    const float* bgat   = (const float*)d_in[6];
    const float* bn1w   = (const float*)d_in[7];
    const float* bn1b   = (const float*)d_in[8];
    const float* Wgcn   = (const float*)d_in[9];
    const float* bgcn   = (const float*)d_in[10];
    const float* bn2w   = (const float*)d_in[11];
    const float* bn2b   = (const float*)d_in[12];
    const float* Wgate  = (const float*)d_in[13];
    const float* bgate  = (const float*)d_in[14];
    const float* Wfc    = (const float*)d_in[15];
    const float* bfc    = (const float*)d_in[16];
    float* out = (float*)d_out;

    int n = in_sizes[0] / 128;
    int e = in_sizes[1] / 2;
    if (n > MAXN) n = MAXN;
    if (e > MAXE) e = MAXE;
    const int* src = ei;
    const int* dst = ei + e;

    float *ph, *pout1, *ph2;
    cudaGetSymbolAddress((void**)&ph,    g_h);
    cudaGetSymbolAddress((void**)&pout1, g_out1);
    cudaGetSymbolAddress((void**)&ph2,   g_h2);

    int nb = (n + 1023) / 1024;

    k_init <<<(n + 255) / 256, 256>>>(n);
    k_count<<<(e + 255) / 256, 256>>>(dst, e);
    k_scan1<<<nb, 1024>>>(n);
    k_scan2<<<1, 64>>>(nb);
    k_scan3<<<nb, 1024>>>(n);
    k_fill <<<(e + 255) / 256, 256>>>(src, dst, e);

    k_gemm128<true><<<(n + 127) / 128, 256>>>(x, Wgat, ph, attsrc, attdst, n);
    k_gat<<<(n * 32 + 255) / 256, 256>>>(bgat, bn1w, bn1b, n);

    k_gemm128<false><<<(n + 127) / 128, 256>>>(pout1, Wgcn, ph2, nullptr, nullptr, n);
    k_gcn<<<(n * 32 + 255) / 256, 256>>>(bgcn, bn2w, bn2b, Wgate, bgate, batch, n);

    k_pool<<<(n + 63) / 64, 128>>>(batch, n);
    k_final<<<NSEG, 128>>>(Wfc, bfc, out);
}

// round 16
// speedup vs baseline: 1.6973x; 1.3252x over previous
#include <cuda_runtime.h>
#include <math.h>

#define MAXN 50000
#define MAXE 800000
#define NSEG 64

// ---------------- scratch (device globals; no allocations allowed) ----------
__device__ int      g_cnt[MAXN];
__device__ int      g_rowptr[MAXN + 1];
__device__ int      g_cursor[MAXN];
__device__ int      g_col[MAXE];
__device__ int      g_bsums[64];
__device__ int      g_boff[65];
__device__ float    g_h[MAXN * 128];     // GAT features (x @ W_gat)
__device__ float    g_out1[MAXN * 128];  // post-GAT node features
__device__ float    g_h2[MAXN * 128];    // out1 @ W_gcn
__device__ float    g_out2[MAXN * 128];  // post-GCN node features
__device__ float    g_asrc[MAXN * 4];
__device__ float    g_adst[MAXN * 4];
__device__ float    g_dinv[MAXN];
__device__ float    g_gate[MAXN];
__device__ unsigned g_gmax[NSEG];
__device__ float    g_gsum[NSEG];
__device__ float    g_grep[NSEG * 128];

// ---------------- helpers ----------------------------------------------------
__device__ __forceinline__ float lrelu(float x) { return x > 0.f ? x : 0.2f * x; }
__device__ __forceinline__ float elu(float x)   { return x > 0.f ? x : expm1f(x); }
__device__ __forceinline__ float sel4(float4 v, int h) {
    return h == 0 ? v.x : h == 1 ? v.y : h == 2 ? v.z : v.w;
}
__device__ __forceinline__ unsigned fenc(float f) {
    unsigned u = __float_as_uint(f);
    return (u & 0x80000000u) ? ~u : (u | 0x80000000u);
}
__device__ __forceinline__ float fdec(unsigned u) {
    return (u & 0x80000000u) ? __uint_as_float(u ^ 0x80000000u) : __uint_as_float(~u);
}
__device__ __forceinline__ void onl(float& m, float& s, float v) {
    float nm = fmaxf(m, v);
    s = s * __expf(m - nm) + __expf(v - nm);
    m = nm;
}
__device__ __forceinline__ void comb(float& m, float& s, float mo, float so) {
    float nm = fmaxf(m, mo);
    s = s * __expf(m - nm) + so * __expf(mo - nm);
    m = nm;
}
__device__ __forceinline__ unsigned f2tf(float f) {
    unsigned u;
    asm("cvt.rna.tf32.f32 %0, %1;" : "=r"(u) : "f"(f));
    return u;
}
__device__ __forceinline__ void mma_tf32(float c[4], const unsigned a[4], const unsigned b[2]) {
    asm("mma.sync.aligned.m16n8k8.row.col.f32.tf32.tf32.f32 "
        "{%0,%1,%2,%3},{%4,%5,%6,%7},{%8,%9},{%0,%1,%2,%3};"
        : "+f"(c[0]), "+f"(c[1]), "+f"(c[2]), "+f"(c[3])
        : "r"(a[0]), "r"(a[1]), "r"(a[2]), "r"(a[3]), "r"(b[0]), "r"(b[1]));
}

// ---------------- init --------------------------------------------------------
__global__ void k_init(int n) {
    int i = blockIdx.x * blockDim.x + threadIdx.x;
    if (i < n) g_cnt[i] = 0;
    if (i < NSEG) { g_gmax[i] = 0x007FFFFFu; g_gsum[i] = 0.f; }  // enc(-inf)
    if (i < NSEG * 128) g_grep[i] = 0.f;
}

// ---------------- CSR build ----------------------------------------------------
__global__ void k_count(const int* __restrict__ dst, int e) {
    int i = blockIdx.x * blockDim.x + threadIdx.x;
    if (i < e) atomicAdd(&g_cnt[dst[i]], 1);
}

__global__ void k_scan1(int n) {
    int tid = threadIdx.x;
    int gid = blockIdx.x * 1024 + tid;
    int v = (gid < n) ? g_cnt[gid] : 0;
    int x = v;
    int lane = tid & 31, wid = tid >> 5;
    #pragma unroll
    for (int off = 1; off < 32; off <<= 1) {
        int y = __shfl_up_sync(0xFFFFFFFFu, x, off);
        if (lane >= off) x += y;
    }
    __shared__ int ws[32];
    if (lane == 31) ws[wid] = x;
    __syncthreads();
    if (wid == 0) {
        int s = ws[lane];
        #pragma unroll
        for (int off = 1; off < 32; off <<= 1) {
            int y = __shfl_up_sync(0xFFFFFFFFu, s, off);
            if (lane >= off) s += y;
        }
        ws[lane] = s;
    }
    __syncthreads();
    int add = wid ? ws[wid - 1] : 0;
    int incl = x + add;
    if (gid < n) g_rowptr[gid] = incl - v;
    if (tid == 1023) g_bsums[blockIdx.x] = incl;
}

__global__ void k_scan2(int nb) {
    int tid = threadIdx.x;
    int lane = tid & 31, w = tid >> 5;
    int v = (tid < nb) ? g_bsums[tid] : 0;
    int x = v;
    #pragma unroll
    for (int off = 1; off < 32; off <<= 1) {
        int y = __shfl_up_sync(0xFFFFFFFFu, x, off);
        if (lane >= off) x += y;
    }
    __shared__ int t0;
    if (w == 0 && lane == 31) t0 = x;
    __syncthreads();
    if (w == 1) x += t0;
    g_boff[tid + 1] = x;
    if (tid == 0) g_boff[0] = 0;
}

__global__ void k_scan3(int n) {
    int gid = blockIdx.x * 1024 + threadIdx.x;
    if (gid < n) {
        int v = g_rowptr[gid] + g_boff[blockIdx.x];
        g_rowptr[gid] = v;
        g_cursor[gid] = v;
    }
    if (gid == 0) g_rowptr[n] = g_boff[gridDim.x];
}

__global__ void k_fill(const int* __restrict__ src, const int* __restrict__ dst, int e) {
    int i = blockIdx.x * blockDim.x + threadIdx.x;
    if (i < e) {
        int d = dst[i];
        int p = atomicAdd(&g_cursor[d], 1);
        g_col[p] = src[i];
    }
}

// ---------------- tf32 tensor-core GEMM: C[n,128] = A[n,128] @ B[128,128] -------
// 256 threads = 8 warps in 4x2 (M x N); warp tile 32x64; k staged in chunks of 32.
// Shared holds pre-converted tf32 bits; padded strides (36 / 136) are
// conflict-free for the fragment gather patterns.
__global__ __launch_bounds__(256, 2) void k_gemm_tf32(
    const float* __restrict__ A, const float* __restrict__ B,
    float* __restrict__ C, int n) {
    __shared__ unsigned As[128 * 36];   // [row][k] stride 36
    __shared__ unsigned Bs[32 * 136];   // [k][col] stride 136
    int tid = threadIdx.x;
    int lane = tid & 31;
    int warp = tid >> 5;
    int warpM = warp & 3;    // 0..3 -> rows warpM*32
    int warpN = warp >> 2;   // 0..1 -> cols warpN*64
    int rowBase = blockIdx.x * 128;

    float c[2][8][4];
    #pragma unroll
    for (int m = 0; m < 2; m++)
        #pragma unroll
        for (int na = 0; na < 8; na++)
            #pragma unroll
            for (int q = 0; q < 4; q++) c[m][na][q] = 0.f;

    for (int kc = 0; kc < 4; kc++) {
        // stage A chunk [128 x 32] (1024 float4 total, 4 per thread)
        #pragma unroll
        for (int f = tid; f < 1024; f += 256) {
            int row = f >> 3, cc = (f & 7) * 4;
            int gr = rowBase + row;
            float4 v = make_float4(0.f, 0.f, 0.f, 0.f);
            if (gr < n) v = *(const float4*)&A[(long)gr * 128 + kc * 32 + cc];
            uint4 u = make_uint4(f2tf(v.x), f2tf(v.y), f2tf(v.z), f2tf(v.w));
            *(uint4*)&As[row * 36 + cc] = u;
        }
        // stage B chunk [32 x 128]
        #pragma unroll
        for (int f = tid; f < 1024; f += 256) {
            int row = f >> 5, cc = (f & 31) * 4;
            float4 v = *(const float4*)&B[(long)(kc * 32 + row) * 128 + cc];
            uint4 u = make_uint4(f2tf(v.x), f2tf(v.y), f2tf(v.z), f2tf(v.w));
            *(uint4*)&Bs[row * 136 + cc] = u;
        }
        __syncthreads();
        #pragma unroll
        for (int ks = 0; ks < 4; ks++) {
            int kk = ks * 8 + (lane & 3);
            int r0 = warpM * 32 + (lane >> 2);
            unsigned a[2][4];
            a[0][0] = As[r0 * 36 + kk];
            a[0][1] = As[(r0 + 8) * 36 + kk];
            a[0][2] = As[r0 * 36 + kk + 4];
            a[0][3] = As[(r0 + 8) * 36 + kk + 4];
            a[1][0] = As[(r0 + 16) * 36 + kk];
            a[1][1] = As[(r0 + 24) * 36 + kk];
            a[1][2] = As[(r0 + 16) * 36 + kk + 4];
            a[1][3] = As[(r0 + 24) * 36 + kk + 4];
            int cb = warpN * 64 + (lane >> 2);
            unsigned b[8][2];
            #pragma unroll
            for (int na = 0; na < 8; na++) {
                b[na][0] = Bs[kk * 136 + cb + na * 8];
                b[na][1] = Bs[(kk + 4) * 136 + cb + na * 8];
            }
            #pragma unroll
            for (int m = 0; m < 2; m++)
                #pragma unroll
                for (int na = 0; na < 8; na++)
                    mma_tf32(c[m][na], a[m], b[na]);
        }
        __syncthreads();
    }

    // epilogue: c0,c1 at (row, col..col+1); c2,c3 at (row+8, col..col+1)
    int rr = rowBase + warpM * 32 + (lane >> 2);
    int cc0 = warpN * 64 + 2 * (lane & 3);
    #pragma unroll
    for (int m = 0; m < 2; m++) {
        int r = rr + m * 16;
        #pragma unroll
        for (int na = 0; na < 8; na++) {
            int col = cc0 + na * 8;
            if (r < n)     *(float2*)&C[(long)r * 128 + col]       = make_float2(c[m][na][0], c[m][na][1]);
            if (r + 8 < n) *(float2*)&C[(long)(r + 8) * 128 + col] = make_float2(c[m][na][2], c[m][na][3]);
        }
    }
}

// ---------------- attention logits per node ------------------------------------
__global__ void k_attn(const float* __restrict__ attsrc, const float* __restrict__ attdst, int n) {
    int w = (blockIdx.x * blockDim.x + threadIdx.x) >> 5;
    int lane = threadIdx.x & 31;
    if (w >= n) return;
    float4 hv = *(const float4*)&g_h[(long)w * 128 + lane * 4];
    float4 s4 = *(const float4*)&attsrc[lane * 4];
    float4 d4 = *(const float4*)&attdst[lane * 4];
    float ps = hv.x * s4.x + hv.y * s4.y + hv.z * s4.z + hv.w * s4.w;
    float pd = hv.x * d4.x + hv.y * d4.y + hv.z * d4.z + hv.w * d4.w;
    #pragma unroll
    for (int off = 4; off; off >>= 1) {
        ps += __shfl_xor_sync(0xFFFFFFFFu, ps, off);
        pd += __shfl_xor_sync(0xFFFFFFFFu, pd, off);
    }
    if ((lane & 7) == 0) {
        g_asrc[w * 4 + (lane >> 3)] = ps;
        g_adst[w * 4 + (lane >> 3)] = pd;
    }
}

// ---------------- GAT aggregation: warp per dst node, online softmax ------------
__global__ __launch_bounds__(256) void k_gat(
    const float* __restrict__ b_gat, const float* __restrict__ bn1w,
    const float* __restrict__ bn1b, int n) {
    int i = (blockIdx.x * blockDim.x + threadIdx.x) >> 5;
    int lane = threadIdx.x & 31;
    if (i >= n) return;
    int beg = g_rowptr[i], end = g_rowptr[i + 1];

    float4 ad  = *(const float4*)&g_adst[i * 4];
    float4 asi = *(const float4*)&g_asrc[i * 4];
    float4 sl;
    sl.x = lrelu(asi.x + ad.x); sl.y = lrelu(asi.y + ad.y);
    sl.z = lrelu(asi.z + ad.z); sl.w = lrelu(asi.w + ad.w);

    float4 mx, sm;
    if (lane == 0) { mx = sl; sm = make_float4(1.f, 1.f, 1.f, 1.f); }
    else { mx = make_float4(-1e30f, -1e30f, -1e30f, -1e30f);
           sm = make_float4(0.f, 0.f, 0.f, 0.f); }
    for (int e = beg + lane; e < end; e += 32) {
        int s = g_col[e];
        float4 v = *(const float4*)&g_asrc[s * 4];
        onl(mx.x, sm.x, lrelu(v.x + ad.x));
        onl(mx.y, sm.y, lrelu(v.y + ad.y));
        onl(mx.z, sm.z, lrelu(v.z + ad.z));
        onl(mx.w, sm.w, lrelu(v.w + ad.w));
    }
    #pragma unroll
    for (int off = 16; off; off >>= 1) {
        float mox = __shfl_xor_sync(0xFFFFFFFFu, mx.x, off);
        float sox = __shfl_xor_sync(0xFFFFFFFFu, sm.x, off);
        float moy = __shfl_xor_sync(0xFFFFFFFFu, mx.y, off);
        float soy = __shfl_xor_sync(0xFFFFFFFFu, sm.y, off);
        float moz = __shfl_xor_sync(0xFFFFFFFFu, mx.z, off);
        float soz = __shfl_xor_sync(0xFFFFFFFFu, sm.z, off);
        float mow = __shfl_xor_sync(0xFFFFFFFFu, mx.w, off);
        float sow = __shfl_xor_sync(0xFFFFFFFFu, sm.w, off);
        comb(mx.x, sm.x, mox, sox);
        comb(mx.y, sm.y, moy, soy);
        comb(mx.z, sm.z, moz, soz);
        comb(mx.w, sm.w, mow, sow);
    }
    sm.x += 1e-16f; sm.y += 1e-16f; sm.z += 1e-16f; sm.w += 1e-16f;

    int head = lane >> 3;
    float m_h  = sel4(mx, head);
    float inv  = 1.f / sel4(sm, head);
    float ad_h = sel4(ad, head);

    const float4* hf = (const float4*)g_h;
    float a_self = __expf(sel4(sl, head) - m_h) * inv;
    float4 hv = hf[(long)i * 32 + lane];
    float4 acc = make_float4(a_self * hv.x, a_self * hv.y, a_self * hv.z, a_self * hv.w);

    int sA = (beg < end) ? g_col[beg] : 0;
    for (int e = beg; e < end; e++) {
        int s = sA;
        if (e + 1 < end) sA = g_col[e + 1];
        float a = lrelu(g_asrc[s * 4 + head] + ad_h);
        float alpha = __expf(a - m_h) * inv;
        float4 v = hf[(long)s * 32 + lane];
        acc.x += alpha * v.x; acc.y += alpha * v.y;
        acc.z += alpha * v.z; acc.w += alpha * v.w;
    }

    float4 bb = ((const float4*)b_gat)[lane];
    float4 w1 = ((const float4*)bn1w)[lane];
    float4 b1 = ((const float4*)bn1b)[lane];
    float4 o;
    o.x = elu(acc.x + bb.x) * w1.x + b1.x;
    o.y = elu(acc.y + bb.y) * w1.y + b1.y;
    o.z = elu(acc.z + bb.z) * w1.z + b1.z;
    o.w = elu(acc.w + bb.w) * w1.w + b1.w;
    ((float4*)g_out1)[(long)i * 32 + lane] = o;
    if (lane == 0) g_dinv[i] = rsqrtf((float)(end - beg + 1));
}

// ---------------- GCN aggregation + gate + pool max -----------------------------
__global__ __launch_bounds__(256) void k_gcn(
    const float* __restrict__ b_gcn, const float* __restrict__ bn2w,
    const float* __restrict__ bn2b, const float* __restrict__ Wgate,
    const float* __restrict__ bgate, const int* __restrict__ batch, int n) {
    int i = (blockIdx.x * blockDim.x + threadIdx.x) >> 5;
    int lane = threadIdx.x & 31;
    if (i >= n) return;
    int beg = g_rowptr[i], end = g_rowptr[i + 1];
    float di = g_dinv[i];
    const float4* h2 = (const float4*)g_h2;

    float4 v = h2[(long)i * 32 + lane];
    float s2 = di * di;
    float4 acc = make_float4(s2 * v.x, s2 * v.y, s2 * v.z, s2 * v.w);

    int sA = (beg < end) ? g_col[beg] : 0;
    for (int e = beg; e < end; e++) {
        int s = sA;
        if (e + 1 < end) sA = g_col[e + 1];
        float nm = di * g_dinv[s];
        float4 u = h2[(long)s * 32 + lane];
        acc.x += nm * u.x; acc.y += nm * u.y;
        acc.z += nm * u.z; acc.w += nm * u.w;
    }

    float4 bb = ((const float4*)b_gcn)[lane];
    float4 w2 = ((const float4*)bn2w)[lane];
    float4 b2 = ((const float4*)bn2b)[lane];
    float4 o;
    o.x = elu(acc.x + bb.x) * w2.x + b2.x;
    o.y = elu(acc.y + bb.y) * w2.y + b2.y;
    o.z = elu(acc.z + bb.z) * w2.z + b2.z;
    o.w = elu(acc.w + bb.w) * w2.w + b2.w;
    ((float4*)g_out2)[(long)i * 32 + lane] = o;

    float4 wg = ((const float4*)Wgate)[lane];
    float g = o.x * wg.x + o.y * wg.y + o.z * wg.z + o.w * wg.w;
    #pragma unroll
    for (int off = 16; off; off >>= 1) g += __shfl_xor_sync(0xFFFFFFFFu, g, off);
    if (lane == 0) {
        float gg = g + bgate[0];
        g_gate[i] = gg;
        atomicMax(&g_gmax[batch[i]], fenc(gg));
    }
}

// ---------------- pooling: block-local accumulation (batch is sorted) -----------
__global__ __launch_bounds__(128) void k_pool(const int* __restrict__ batch, int n) {
    int c = threadIdx.x;
    int nbeg = blockIdx.x * 64;
    int nend = nbeg + 64; if (nend > n) nend = n;
    if (nbeg >= n) return;
    int curb = batch[nbeg];
    float m = fdec(g_gmax[curb]); if (!isfinite(m)) m = 0.f;
    float acc = 0.f, exsum = 0.f;
    for (int nn = nbeg; nn < nend; nn++) {
        int b = batch[nn];
        if (b != curb) {
            atomicAdd(&g_grep[curb * 128 + c], acc);
            if (c == 0) atomicAdd(&g_gsum[curb], exsum);
            acc = 0.f; exsum = 0.f; curb = b;
            m = fdec(g_gmax[curb]); if (!isfinite(m)) m = 0.f;
        }
        float ex = __expf(g_gate[nn] - m);
        exsum += ex;
        acc += ex * g_out2[(long)nn * 128 + c];
    }
    atomicAdd(&g_grep[curb * 128 + c], acc);
    if (c == 0) atomicAdd(&g_gsum[curb], exsum);
}

__global__ void k_final(const float* __restrict__ Wfc, const float* __restrict__ bfc,
                        float* __restrict__ out) {
    int g = blockIdx.x;
    int t = threadIdx.x;  // 128
    float v = g_grep[g * 128 + t] * Wfc[t];
    #pragma unroll
    for (int off = 16; off; off >>= 1) v += __shfl_xor_sync(0xFFFFFFFFu, v, off);
    __shared__ float s[4];
    if ((t & 31) == 0) s[t >> 5] = v;
    __syncthreads();
    if (t == 0) out[g] = (s[0] + s[1] + s[2] + s[3]) / (g_gsum[g] + 1e-16f) + bfc[0];
}

// ---------------- launcher ------------------------------------------------------
extern "C" void kernel_launch(void* const* d_in, const int* in_sizes, int n_in,
                              void* d_out, int out_size) {
    const float* x      = (const float*)d_in[0];
    const int*   ei     = (const int*)  d_in[1];
    const int*   batch  = (const int*)  d_in[2];
    const float* Wgat   = (const float*)d_in[3];
    const float* attsrc = (const float*)d_in[4];
    const float* attdst = (const float*)d_in[5];
    const float* bgat   = (const float*)d_in[6];
    const float* bn1w   = (const float*)d_in[7];
    const float* bn1b   = (const float*)d_in[8];
    const float* Wgcn   = (const float*)d_in[9];
    const float* bgcn   = (const float*)d_in[10];
    const float* bn2w   = (const float*)d_in[11];
    const float* bn2b   = (const float*)d_in[12];
    const float* Wgate  = (const float*)d_in[13];
    const float* bgate  = (const float*)d_in[14];
    const float* Wfc    = (const float*)d_in[15];
    const float* bfc    = (const float*)d_in[16];
    float* out = (float*)d_out;

    int n = in_sizes[0] / 128;
    int e = in_sizes[1] / 2;
    if (n > MAXN) n = MAXN;
    if (e > MAXE) e = MAXE;
    const int* src = ei;
    const int* dst = ei + e;

    float *ph, *pout1, *ph2;
    cudaGetSymbolAddress((void**)&ph,    g_h);
    cudaGetSymbolAddress((void**)&pout1, g_out1);
    cudaGetSymbolAddress((void**)&ph2,   g_h2);

    int nb = (n + 1023) / 1024;

    k_init <<<(n + 255) / 256, 256>>>(n);
    k_count<<<(e + 255) / 256, 256>>>(dst, e);
    k_scan1<<<nb, 1024>>>(n);
    k_scan2<<<1, 64>>>(nb);
    k_scan3<<<nb, 1024>>>(n);
    k_fill <<<(e + 255) / 256, 256>>>(src, dst, e);

    k_gemm_tf32<<<(n + 127) / 128, 256>>>(x, Wgat, ph, n);
    k_attn<<<(n * 32 + 255) / 256, 256>>>(attsrc, attdst, n);
    k_gat<<<(n * 32 + 255) / 256, 256>>>(bgat, bn1w, bn1b, n);

    k_gemm_tf32<<<(n + 127) / 128, 256>>>(pout1, Wgcn, ph2, n);
    k_gcn<<<(n * 32 + 255) / 256, 256>>>(bgcn, bn2w, bn2b, Wgate, bgate, batch, n);

    k_pool<<<(n + 63) / 64, 128>>>(batch, n);
    k_final<<<NSEG, 128>>>(Wfc, bfc, out);
}

// round 17
// speedup vs baseline: 1.7163x; 1.0112x over previous
#include <cuda_runtime.h>
#include <cuda_fp16.h>
#include <math.h>

#define MAXN 50000
#define MAXE 800000
#define NSEG 64

// ---------------- scratch (device globals; no allocations allowed) ----------
__device__ int      g_cnt[MAXN];
__device__ int      g_rowptr[MAXN + 1];
__device__ int      g_cursor[MAXN];
__device__ int      g_col[MAXE];
__device__ int      g_pub[64];           // scan: aggregate+1 (0 = not ready)
__device__ __half   g_h16[MAXN * 128];   // GAT features (x @ W_gat), fp16
__device__ float    g_out1[MAXN * 128];  // post-GAT node features
__device__ __half   g_h216[MAXN * 128];  // out1 @ W_gcn, fp16
__device__ float    g_out2[MAXN * 128];  // post-GCN node features
__device__ float    g_asrc[MAXN * 4];
__device__ float    g_adst[MAXN * 4];
__device__ float    g_dinv[MAXN];
__device__ float    g_gate[MAXN];
__device__ unsigned g_gmax[NSEG];
__device__ float    g_gsum[NSEG];
__device__ float    g_grep[NSEG * 128];

// ---------------- helpers ----------------------------------------------------
__device__ __forceinline__ float lrelu(float x) { return x > 0.f ? x : 0.2f * x; }
__device__ __forceinline__ float elu(float x)   { return x > 0.f ? x : expm1f(x); }
__device__ __forceinline__ float sel4(float4 v, int h) {
    return h == 0 ? v.x : h == 1 ? v.y : h == 2 ? v.z : v.w;
}
__device__ __forceinline__ unsigned fenc(float f) {
    unsigned u = __float_as_uint(f);
    return (u & 0x80000000u) ? ~u : (u | 0x80000000u);
}
__device__ __forceinline__ float fdec(unsigned u) {
    return (u & 0x80000000u) ? __uint_as_float(u ^ 0x80000000u) : __uint_as_float(~u);
}
__device__ __forceinline__ void onl(float& m, float& s, float v) {
    float nm = fmaxf(m, v);
    s = s * __expf(m - nm) + __expf(v - nm);
    m = nm;
}
__device__ __forceinline__ void comb(float& m, float& s, float mo, float so) {
    float nm = fmaxf(m, mo);
    s = s * __expf(m - nm) + so * __expf(mo - nm);
    m = nm;
}
__device__ __forceinline__ unsigned f2tf(float f) {
    unsigned u;
    asm("cvt.rna.tf32.f32 %0, %1;" : "=r"(u) : "f"(f));
    return u;
}
__device__ __forceinline__ void mma_tf32(float c[4], const unsigned a[4], const unsigned b[2]) {
    asm("mma.sync.aligned.m16n8k8.row.col.f32.tf32.tf32.f32 "
        "{%0,%1,%2,%3},{%4,%5,%6,%7},{%8,%9},{%0,%1,%2,%3};"
        : "+f"(c[0]), "+f"(c[1]), "+f"(c[2]), "+f"(c[3])
        : "r"(a[0]), "r"(a[1]), "r"(a[2]), "r"(a[3]), "r"(b[0]), "r"(b[1]));
}
// load 4 halves (8B) and convert to float4
__device__ __forceinline__ float4 ldh4(const __half* p) {
    uint2 u = *(const uint2*)p;
    __half2 a = *(__half2*)&u.x;
    __half2 b = *(__half2*)&u.y;
    float2 fa = __half22float2(a);
    float2 fb = __half22float2(b);
    return make_float4(fa.x, fa.y, fb.x, fb.y);
}

// ---------------- init --------------------------------------------------------
__global__ void k_init(int n) {
    int i = blockIdx.x * blockDim.x + threadIdx.x;
    if (i < n) g_cnt[i] = 0;
    if (i < 64) g_pub[i] = 0;
    if (i < NSEG) { g_gmax[i] = 0x007FFFFFu; g_gsum[i] = 0.f; }  // enc(-inf)
    if (i < NSEG * 128) g_grep[i] = 0.f;
}

// ---------------- CSR build ----------------------------------------------------
__global__ void k_count(const int* __restrict__ dst, int e) {
    int i = blockIdx.x * blockDim.x + threadIdx.x;
    if (i < e) atomicAdd(&g_cnt[dst[i]], 1);
}

// single-kernel scan with decoupled lookback (one wave: <=49 blocks, all resident)
__global__ __launch_bounds__(1024) void k_scan(int n) {
    int tid = threadIdx.x;
    int b = blockIdx.x;
    int gid = b * 1024 + tid;
    int v = (gid < n) ? g_cnt[gid] : 0;
    int x = v;
    int lane = tid & 31, wid = tid >> 5;
    #pragma unroll
    for (int off = 1; off < 32; off <<= 1) {
        int y = __shfl_up_sync(0xFFFFFFFFu, x, off);
        if (lane >= off) x += y;
    }
    __shared__ int ws[32];
    if (lane == 31) ws[wid] = x;
    __syncthreads();
    if (wid == 0) {
        int s = ws[lane];
        #pragma unroll
        for (int off = 1; off < 32; off <<= 1) {
            int y = __shfl_up_sync(0xFFFFFFFFu, s, off);
            if (lane >= off) s += y;
        }
        ws[lane] = s;
    }
    __syncthreads();
    int incl = x + (wid ? ws[wid - 1] : 0);   // block-inclusive

    // publish this block's aggregate (value+1; 0 means not ready)
    if (tid == 1023) atomicExch(&g_pub[b], incl + 1);

    // lookback: sum aggregates of blocks [0, b)
    __shared__ int s_off;
    if (tid < 32) {
        int sum = 0;
        for (int j = lane; j < b; j += 32) {
            int p;
            do { p = atomicAdd(&g_pub[j], 0); } while (p == 0);
            sum += p - 1;
        }
        #pragma unroll
        for (int off = 16; off; off >>= 1) sum += __shfl_xor_sync(0xFFFFFFFFu, sum, off);
        if (lane == 0) s_off = sum;
    }
    __syncthreads();
    int excl = s_off + incl - v;
    if (gid < n) { g_rowptr[gid] = excl; g_cursor[gid] = excl; }
    if (b == gridDim.x - 1 && tid == 1023) g_rowptr[n] = s_off + incl;
}

__global__ void k_fill(const int* __restrict__ src, const int* __restrict__ dst, int e) {
    int i = blockIdx.x * blockDim.x + threadIdx.x;
    if (i < e) {
        int d = dst[i];
        int p = atomicAdd(&g_cursor[d], 1);
        g_col[p] = src[i];
    }
}

// ---------------- tf32 tensor-core GEMM: C[n,128] = A[n,128] @ B[128,128] -------
// Output written as fp16 (half2 pairs). 8 warps 4x2, warp tile 32x64, k-chunk 32.
__global__ __launch_bounds__(256, 2) void k_gemm_tf32(
    const float* __restrict__ A, const float* __restrict__ B,
    __half* __restrict__ C16, int n) {
    __shared__ unsigned As[128 * 36];   // [row][k] stride 36
    __shared__ unsigned Bs[32 * 136];   // [k][col] stride 136
    int tid = threadIdx.x;
    int lane = tid & 31;
    int warp = tid >> 5;
    int warpM = warp & 3;
    int warpN = warp >> 2;
    int rowBase = blockIdx.x * 128;

    float c[2][8][4];
    #pragma unroll
    for (int m = 0; m < 2; m++)
        #pragma unroll
        for (int na = 0; na < 8; na++)
            #pragma unroll
            for (int q = 0; q < 4; q++) c[m][na][q] = 0.f;

    for (int kc = 0; kc < 4; kc++) {
        #pragma unroll
        for (int f = tid; f < 1024; f += 256) {
            int row = f >> 3, cc = (f & 7) * 4;
            int gr = rowBase + row;
            float4 v = make_float4(0.f, 0.f, 0.f, 0.f);
            if (gr < n) v = *(const float4*)&A[(long)gr * 128 + kc * 32 + cc];
            uint4 u = make_uint4(f2tf(v.x), f2tf(v.y), f2tf(v.z), f2tf(v.w));
            *(uint4*)&As[row * 36 + cc] = u;
        }
        #pragma unroll
        for (int f = tid; f < 1024; f += 256) {
            int row = f >> 5, cc = (f & 31) * 4;
            float4 v = *(const float4*)&B[(long)(kc * 32 + row) * 128 + cc];
            uint4 u = make_uint4(f2tf(v.x), f2tf(v.y), f2tf(v.z), f2tf(v.w));
            *(uint4*)&Bs[row * 136 + cc] = u;
        }
        __syncthreads();
        #pragma unroll
        for (int ks = 0; ks < 4; ks++) {
            int kk = ks * 8 + (lane & 3);
            int r0 = warpM * 32 + (lane >> 2);
            unsigned a[2][4];
            a[0][0] = As[r0 * 36 + kk];
            a[0][1] = As[(r0 + 8) * 36 + kk];
            a[0][2] = As[r0 * 36 + kk + 4];
            a[0][3] = As[(r0 + 8) * 36 + kk + 4];
            a[1][0] = As[(r0 + 16) * 36 + kk];
            a[1][1] = As[(r0 + 24) * 36 + kk];
            a[1][2] = As[(r0 + 16) * 36 + kk + 4];
            a[1][3] = As[(r0 + 24) * 36 + kk + 4];
            int cb = warpN * 64 + (lane >> 2);
            unsigned b[8][2];
            #pragma unroll
            for (int na = 0; na < 8; na++) {
                b[na][0] = Bs[kk * 136 + cb + na * 8];
                b[na][1] = Bs[(kk + 4) * 136 + cb + na * 8];
            }
            #pragma unroll
            for (int m = 0; m < 2; m++)
                #pragma unroll
                for (int na = 0; na < 8; na++)
                    mma_tf32(c[m][na], a[m], b[na]);
        }
        __syncthreads();
    }

    int rr = rowBase + warpM * 32 + (lane >> 2);
    int cc0 = warpN * 64 + 2 * (lane & 3);
    #pragma unroll
    for (int m = 0; m < 2; m++) {
        int r = rr + m * 16;
        #pragma unroll
        for (int na = 0; na < 8; na++) {
            int col = cc0 + na * 8;
            if (r < n)
                *(__half2*)&C16[(long)r * 128 + col] =
                    __float22half2_rn(make_float2(c[m][na][0], c[m][na][1]));
            if (r + 8 < n)
                *(__half2*)&C16[(long)(r + 8) * 128 + col] =
                    __float22half2_rn(make_float2(c[m][na][2], c[m][na][3]));
        }
    }
}

// ---------------- attention logits per node ------------------------------------
__global__ void k_attn(const float* __restrict__ attsrc, const float* __restrict__ attdst, int n) {
    int w = (blockIdx.x * blockDim.x + threadIdx.x) >> 5;
    int lane = threadIdx.x & 31;
    if (w >= n) return;
    float4 hv = ldh4(&g_h16[(long)w * 128 + lane * 4]);
    float4 s4 = *(const float4*)&attsrc[lane * 4];
    float4 d4 = *(const float4*)&attdst[lane * 4];
    float ps = hv.x * s4.x + hv.y * s4.y + hv.z * s4.z + hv.w * s4.w;
    float pd = hv.x * d4.x + hv.y * d4.y + hv.z * d4.z + hv.w * d4.w;
    #pragma unroll
    for (int off = 4; off; off >>= 1) {
        ps += __shfl_xor_sync(0xFFFFFFFFu, ps, off);
        pd += __shfl_xor_sync(0xFFFFFFFFu, pd, off);
    }
    if ((lane & 7) == 0) {
        g_asrc[w * 4 + (lane >> 3)] = ps;
        g_adst[w * 4 + (lane >> 3)] = pd;
    }
}

// ---------------- GAT aggregation: warp per dst node, online softmax ------------
__global__ __launch_bounds__(256) void k_gat(
    const float* __restrict__ b_gat, const float* __restrict__ bn1w,
    const float* __restrict__ bn1b, int n) {
    int i = (blockIdx.x * blockDim.x + threadIdx.x) >> 5;
    int lane = threadIdx.x & 31;
    if (i >= n) return;
    int beg = g_rowptr[i], end = g_rowptr[i + 1];

    float4 ad  = *(const float4*)&g_adst[i * 4];
    float4 asi = *(const float4*)&g_asrc[i * 4];
    float4 sl;
    sl.x = lrelu(asi.x + ad.x); sl.y = lrelu(asi.y + ad.y);
    sl.z = lrelu(asi.z + ad.z); sl.w = lrelu(asi.w + ad.w);

    float4 mx, sm;
    if (lane == 0) { mx = sl; sm = make_float4(1.f, 1.f, 1.f, 1.f); }
    else { mx = make_float4(-1e30f, -1e30f, -1e30f, -1e30f);
           sm = make_float4(0.f, 0.f, 0.f, 0.f); }
    for (int e = beg + lane; e < end; e += 32) {
        int s = g_col[e];
        float4 v = *(const float4*)&g_asrc[s * 4];
        onl(mx.x, sm.x, lrelu(v.x + ad.x));
        onl(mx.y, sm.y, lrelu(v.y + ad.y));
        onl(mx.z, sm.z, lrelu(v.z + ad.z));
        onl(mx.w, sm.w, lrelu(v.w + ad.w));
    }
    #pragma unroll
    for (int off = 16; off; off >>= 1) {
        float mox = __shfl_xor_sync(0xFFFFFFFFu, mx.x, off);
        float sox = __shfl_xor_sync(0xFFFFFFFFu, sm.x, off);
        float moy = __shfl_xor_sync(0xFFFFFFFFu, mx.y, off);
        float soy = __shfl_xor_sync(0xFFFFFFFFu, sm.y, off);
        float moz = __shfl_xor_sync(0xFFFFFFFFu, mx.z, off);
        float soz = __shfl_xor_sync(0xFFFFFFFFu, sm.z, off);
        float mow = __shfl_xor_sync(0xFFFFFFFFu, mx.w, off);
        float sow = __shfl_xor_sync(0xFFFFFFFFu, sm.w, off);
        comb(mx.x, sm.x, mox, sox);
        comb(mx.y, sm.y, moy, soy);
        comb(mx.z, sm.z, moz, soz);
        comb(mx.w, sm.w, mow, sow);
    }
    sm.x += 1e-16f; sm.y += 1e-16f; sm.z += 1e-16f; sm.w += 1e-16f;

    int head = lane >> 3;
    float m_h  = sel4(mx, head);
    float inv  = 1.f / sel4(sm, head);
    float ad_h = sel4(ad, head);

    float a_self = __expf(sel4(sl, head) - m_h) * inv;
    float4 hv = ldh4(&g_h16[(long)i * 128 + lane * 4]);
    float4 acc = make_float4(a_self * hv.x, a_self * hv.y, a_self * hv.z, a_self * hv.w);

    int sA = (beg < end) ? g_col[beg] : 0;
    for (int e = beg; e < end; e++) {
        int s = sA;
        if (e + 1 < end) sA = g_col[e + 1];
        float a = lrelu(g_asrc[s * 4 + head] + ad_h);
        float alpha = __expf(a - m_h) * inv;
        float4 v = ldh4(&g_h16[(long)s * 128 + lane * 4]);
        acc.x += alpha * v.x; acc.y += alpha * v.y;
        acc.z += alpha * v.z; acc.w += alpha * v.w;
    }

    float4 bb = ((const float4*)b_gat)[lane];
    float4 w1 = ((const float4*)bn1w)[lane];
    float4 b1 = ((const float4*)bn1b)[lane];
    float4 o;
    o.x = elu(acc.x + bb.x) * w1.x + b1.x;
    o.y = elu(acc.y + bb.y) * w1.y + b1.y;
    o.z = elu(acc.z + bb.z) * w1.z + b1.z;
    o.w = elu(acc.w + bb.w) * w1.w + b1.w;
    ((float4*)g_out1)[(long)i * 32 + lane] = o;
    if (lane == 0) g_dinv[i] = rsqrtf((float)(end - beg + 1));
}

// ---------------- GCN aggregation + gate + pool max -----------------------------
__global__ __launch_bounds__(256) void k_gcn(
    const float* __restrict__ b_gcn, const float* __restrict__ bn2w,
    const float* __restrict__ bn2b, const float* __restrict__ Wgate,
    const float* __restrict__ bgate, const int* __restrict__ batch, int n) {
    int i = (blockIdx.x * blockDim.x + threadIdx.x) >> 5;
    int lane = threadIdx.x & 31;
    if (i >= n) return;
    int beg = g_rowptr[i], end = g_rowptr[i + 1];
    float di = g_dinv[i];

    float4 v = ldh4(&g_h216[(long)i * 128 + lane * 4]);
    float s2 = di * di;
    float4 acc = make_float4(s2 * v.x, s2 * v.y, s2 * v.z, s2 * v.w);

    int sA = (beg < end) ? g_col[beg] : 0;
    for (int e = beg; e < end; e++) {
        int s = sA;
        if (e + 1 < end) sA = g_col[e + 1];
        float nm = di * g_dinv[s];
        float4 u = ldh4(&g_h216[(long)s * 128 + lane * 4]);
        acc.x += nm * u.x; acc.y += nm * u.y;
        acc.z += nm * u.z; acc.w += nm * u.w;
    }

    float4 bb = ((const float4*)b_gcn)[lane];
    float4 w2 = ((const float4*)bn2w)[lane];
    float4 b2 = ((const float4*)bn2b)[lane];
    float4 o;
    o.x = elu(acc.x + bb.x) * w2.x + b2.x;
    o.y = elu(acc.y + bb.y) * w2.y + b2.y;
    o.z = elu(acc.z + bb.z) * w2.z + b2.z;
    o.w = elu(acc.w + bb.w) * w2.w + b2.w;
    ((float4*)g_out2)[(long)i * 32 + lane] = o;

    float4 wg = ((const float4*)Wgate)[lane];
    float g = o.x * wg.x + o.y * wg.y + o.z * wg.z + o.w * wg.w;
    #pragma unroll
    for (int off = 16; off; off >>= 1) g += __shfl_xor_sync(0xFFFFFFFFu, g, off);
    if (lane == 0) {
        float gg = g + bgate[0];
        g_gate[i] = gg;
        atomicMax(&g_gmax[batch[i]], fenc(gg));
    }
}

// ---------------- pooling: block-local accumulation (batch is sorted) -----------
__global__ __launch_bounds__(128) void k_pool(const int* __restrict__ batch, int n) {
    int c = threadIdx.x;
    int nbeg = blockIdx.x * 64;
    int nend = nbeg + 64; if (nend > n) nend = n;
    if (nbeg >= n) return;
    int curb = batch[nbeg];
    float m = fdec(g_gmax[curb]); if (!isfinite(m)) m = 0.f;
    float acc = 0.f, exsum = 0.f;
    for (int nn = nbeg; nn < nend; nn++) {
        int b = batch[nn];
        if (b != curb) {
            atomicAdd(&g_grep[curb * 128 + c], acc);
            if (c == 0) atomicAdd(&g_gsum[curb], exsum);
            acc = 0.f; exsum = 0.f; curb = b;
            m = fdec(g_gmax[curb]); if (!isfinite(m)) m = 0.f;
        }
        float ex = __expf(g_gate[nn] - m);
        exsum += ex;
        acc += ex * g_out2[(long)nn * 128 + c];
    }
    atomicAdd(&g_grep[curb * 128 + c], acc);
    if (c == 0) atomicAdd(&g_gsum[curb], exsum);
}

__global__ void k_final(const float* __restrict__ Wfc, const float* __restrict__ bfc,
                        float* __restrict__ out) {
    int g = blockIdx.x;
    int t = threadIdx.x;  // 128
    float v = g_grep[g * 128 + t] * Wfc[t];
    #pragma unroll
    for (int off = 16; off; off >>= 1) v += __shfl_xor_sync(0xFFFFFFFFu, v, off);
    __shared__ float s[4];
    if ((t & 31) == 0) s[t >> 5] = v;
    __syncthreads();
    if (t == 0) out[g] = (s[0] + s[1] + s[2] + s[3]) / (g_gsum[g] + 1e-16f) + bfc[0];
}

// ---------------- launcher ------------------------------------------------------
extern "C" void kernel_launch(void* const* d_in, const int* in_sizes, int n_in,
                              void* d_out, int out_size) {
    const float* x      = (const float*)d_in[0];
    const int*   ei     = (const int*)  d_in[1];
    const int*   batch  = (const int*)  d_in[2];
    const float* Wgat   = (const float*)d_in[3];
    const float* attsrc = (const float*)d_in[4];
    const float* attdst = (const float*)d_in[5];
    const float* bgat   = (const float*)d_in[6];
    const float* bn1w   = (const float*)d_in[7];
    const float* bn1b   = (const float*)d_in[8];
    const float* Wgcn   = (const float*)d_in[9];
    const float* bgcn   = (const float*)d_in[10];
    const float* bn2w   = (const float*)d_in[11];
    const float* bn2b   = (const float*)d_in[12];
    const float* Wgate  = (const float*)d_in[13];
    const float* bgate  = (const float*)d_in[14];
    const float* Wfc    = (const float*)d_in[15];
    const float* bfc    = (const float*)d_in[16];
    float* out = (float*)d_out;

    int n = in_sizes[0] / 128;
    int e = in_sizes[1] / 2;
    if (n > MAXN) n = MAXN;
    if (e > MAXE) e = MAXE;
    const int* src = ei;
    const int* dst = ei + e;

    __half *ph16, *ph216;
    float *pout1;
    cudaGetSymbolAddress((void**)&ph16,  g_h16);
    cudaGetSymbolAddress((void**)&pout1, g_out1);
    cudaGetSymbolAddress((void**)&ph216, g_h216);

    int nb = (n + 1023) / 1024;

    k_init <<<(n + 255) / 256, 256>>>(n);
    k_count<<<(e + 255) / 256, 256>>>(dst, e);
    k_scan <<<nb, 1024>>>(n);
    k_fill <<<(e + 255) / 256, 256>>>(src, dst, e);

    k_gemm_tf32<<<(n + 127) / 128, 256>>>(x, Wgat, ph16, n);
    k_attn<<<(n * 32 + 255) / 256, 256>>>(attsrc, attdst, n);
    k_gat<<<(n * 32 + 255) / 256, 256>>>(bgat, bn1w, bn1b, n);

    k_gemm_tf32<<<(n + 127) / 128, 256>>>(pout1, Wgcn, ph216, n);
    k_gcn<<<(n * 32 + 255) / 256, 256>>>(bgcn, bn2w, bn2b, Wgate, bgate, batch, n);

    k_pool<<<(n + 63) / 64, 128>>>(batch, n);
    k_final<<<NSEG, 128>>>(Wfc, bfc, out);
}